// round 17
// baseline (speedup 1.0000x reference)
#include <cuda_runtime.h>
#include <cuda_fp16.h>
#include <cstdint>

// Problem constants: B=4, S=2048, D_IN=D_OUT=1024
#define BATCH 4
#define SEQ   2048
#define DIM   1024

// GEMM tiling: CTA 128x128, 256 threads = 8 warps of 64x32 (2x4), K-chunk 128,
// 3 stages -> 204 KB SMEM => 1 CTA/SM (8 warps/SM), 8 barriers per K=1024.
#define ROW_B  272                      // padded row stride bytes (256B data + 16B pad)
#define A_BYTES (128 * ROW_B)           // 34816
#define B_BYTES (128 * ROW_B)           // 34816
#define STG_BYTES (A_BYTES + B_BYTES)   // 69632
#define NSTAGE 3
#define SMEM_TOTAL (NSTAGE * STG_BYTES) // 208896

// V^T epilogue staging tile: 128 d-rows x 136 s-halves (padded)
#define VT_PAD 136

// ---------------- scratch (__device__ globals only) ----------------
__device__ __half g_xh [(long long)BATCH * SEQ * DIM];          // x fp16
__device__ __half g_wt [(long long)3 * DIM * DIM];              // [Wq^T;Wk^T;Wv^T] fp16 [3072,1024]
__device__ float  g_ball[3 * DIM];                              // concat bias
__device__ __half g_qkv[(long long)BATCH * SEQ * 3 * DIM];      // fused QKV out (q,k used; v cols -> vt)
__device__ __half g_vt [(long long)BATCH * DIM * SEQ];          // V^T per batch [1024,2048]
__device__ __half g_p  [(long long)BATCH * SEQ * SEQ];          // unnormalized exp(scores) fp16
__device__ float  g_psum[(long long)BATCH * SEQ * 16];          // per-(row, n-tile) partial sums
__device__ float  g_rowsum[(long long)BATCH * SEQ];             // row sums

// ---------------- helpers ----------------
__device__ __forceinline__ uint32_t smem_u32(const void* p) {
    uint32_t a;
    asm("{ .reg .u64 t; cvta.to.shared.u64 t, %1; cvt.u32.u64 %0, t; }" : "=r"(a) : "l"(p));
    return a;
}

__device__ __forceinline__ void cp16(uint32_t dst, const void* src) {
    asm volatile("cp.async.cg.shared.global [%0], [%1], 16;" :: "r"(dst), "l"(src));
}

__device__ __forceinline__ void ldsm4(uint32_t& r0, uint32_t& r1, uint32_t& r2, uint32_t& r3,
                                      uint32_t addr) {
    asm volatile("ldmatrix.sync.aligned.m8n8.x4.shared.b16 {%0,%1,%2,%3}, [%4];"
                 : "=r"(r0), "=r"(r1), "=r"(r2), "=r"(r3) : "r"(addr));
}

__device__ __forceinline__ void mma16816(float4& d,
                                         uint32_t a0, uint32_t a1, uint32_t a2, uint32_t a3,
                                         uint32_t b0, uint32_t b1) {
    asm volatile(
        "mma.sync.aligned.m16n8k16.row.col.f32.f16.f16.f32 "
        "{%0,%1,%2,%3}, {%4,%5,%6,%7}, {%8,%9}, {%0,%1,%2,%3};"
        : "+f"(d.x), "+f"(d.y), "+f"(d.z), "+f"(d.w)
        : "r"(a0), "r"(a1), "r"(a2), "r"(a3), "r"(b0), "r"(b1));
}

// exp(x) on the FMA pipe (no MUFU). |x| <= ~16 expected; rel err ~1.3e-5.
__device__ __forceinline__ float fast_exp(float x) {
    float t = fmaxf(x * 1.4426950408889634f, -126.0f);
    float n = floorf(t);
    float f = t - n;                       // [0,1)
    float p = 0.00015403530393381608f;
    p = fmaf(p, f, 0.0013333558146428443f);
    p = fmaf(p, f, 0.009618129107628477f);
    p = fmaf(p, f, 0.05550410866482158f);
    p = fmaf(p, f, 0.2402265069591007f);
    p = fmaf(p, f, 0.6931471805599453f);
    p = fmaf(p, f, 1.0f);
    float sc = __int_as_float(((int)n + 127) << 23);
    return p * sc;
}

// ---------------- GEMM: C = scale*(A @ B^T)(+bias) ----------------
// A: [M,K] fp16 K-major. B: [N,K] fp16 K-major. C fp32 or fp16.
// CTA tile 128x128, 256 threads (8 warps as 2x4 grid of 64x32 warp tiles).
// K-chunk 128, 3-stage cp.async pipeline, 1 barrier per chunk.
// vtp != nullptr && n0 >= 2048  : V tile -> stored transposed into vtp.
// DO_EXP: epilogue writes fp16 exp(scale*acc) and per-(row, n-tile) partial
//         sums into psum (deterministic in-order reduction, no atomics).
// rowsum != nullptr (non-DO_EXP): output divided by rowsum[z*SEQ + r].
template <bool HAS_BIAS, bool OUT_HALF, bool DO_EXP>
__global__ __launch_bounds__(256, 1)
void gemm_fp16(const __half* __restrict__ Ag, const __half* __restrict__ Bg,
               const float* __restrict__ bias, void* __restrict__ Cv,
               __half* __restrict__ vtp, float* __restrict__ psum,
               const float* __restrict__ rowsum,
               int K, int lda, int ldb, int ldc,
               long long sA, long long sB, long long sC, float scale) {
    extern __shared__ char smc[];
    const uint32_t sb = smem_u32(smc);
    const int tid = threadIdx.x;
    const int lane = tid & 31, wid = tid >> 5;        // wid 0..7
    const int g = lane >> 2, tg = lane & 3;
    const int mW = (wid >> 2) * 64;                   // 2 warp-rows of 64
    const int nW = (wid & 3) * 32;                    // 4 warp-cols of 32

    Ag += (long long)blockIdx.z * sA;
    Bg += (long long)blockIdx.z * sB;
    const long long cBase = (long long)blockIdx.z * sC;   // element offset into C
    const int m0 = blockIdx.y * 128;
    const int n0 = blockIdx.x * 128;

    // cp.async addressing: rows of 128 halves = 256B = 16 x 16B segments
    const int r16 = tid >> 4;         // 0..15
    const int sg  = tid & 15;
    const __half* aSrc = Ag + (long long)(m0 + r16) * lda + sg * 8;
    const __half* bSrc = Bg + (long long)(n0 + r16) * ldb + sg * 8;

    auto load_chunk = [&](int st, int kc) {
        const uint32_t ab = sb + st * STG_BYTES;
        const uint32_t bb = ab + A_BYTES;
#pragma unroll
        for (int p = 0; p < 8; p++) {     // A: 128 rows, 16 at a time
            const int row = p * 16 + r16;
            cp16(ab + row * ROW_B + sg * 16, aSrc + (long long)p * 16 * lda + kc);
        }
#pragma unroll
        for (int p = 0; p < 8; p++) {     // B: 128 rows
            const int row = p * 16 + r16;
            cp16(bb + row * ROW_B + sg * 16, bSrc + (long long)p * 16 * ldb + kc);
        }
        asm volatile("cp.async.commit_group;" ::: "memory");
    };

    // ldmatrix per-lane byte offsets within stage
    const uint32_t aofs = (mW + (lane & 15)) * ROW_B + (lane >> 4) * 16;
    const uint32_t bofs = (nW + ((lane >> 4) & 1) * 8 + (lane & 7)) * ROW_B
                        + ((lane >> 3) & 1) * 16;

    float4 acc[4][4];
#pragma unroll
    for (int i = 0; i < 4; i++)
#pragma unroll
        for (int j = 0; j < 4; j++)
            acc[i][j] = make_float4(0.f, 0.f, 0.f, 0.f);

    const int NC = K / 128;           // 8 chunks for K=1024
    load_chunk(0, 0);
    load_chunk(1, 128);

    uint32_t af[16], bf[8];

    for (int c = 0; c < NC; c++) {
        // wait until chunk c has landed (<= 1 group still outstanding)
        if (c + 1 < NC) asm volatile("cp.async.wait_group 1;" ::: "memory");
        else            asm volatile("cp.async.wait_group 0;" ::: "memory");
        __syncthreads();   // all warps done with chunk c-1's buffer AND see chunk c

        // prefetch chunk c+2 into the buffer freed by chunk c-1
        if (c + 2 < NC) load_chunk((c + 2) % NSTAGE, (c + 2) * 128);

        const int st = c % NSTAGE;
        const uint32_t aAddr = sb + st * STG_BYTES + aofs;
        const uint32_t bAddr = sb + st * STG_BYTES + A_BYTES + bofs;

#pragma unroll
        for (int ks = 0; ks < 8; ks++) {
            const int kk = ks * 16;
#pragma unroll
            for (int i = 0; i < 4; i++)
                ldsm4(af[i * 4 + 0], af[i * 4 + 1], af[i * 4 + 2], af[i * 4 + 3],
                      aAddr + i * (16 * ROW_B) + kk * 2);
            ldsm4(bf[0], bf[1], bf[2], bf[3], bAddr + kk * 2);
            ldsm4(bf[4], bf[5], bf[6], bf[7], bAddr + 16 * ROW_B + kk * 2);
#pragma unroll
            for (int i = 0; i < 4; i++)
#pragma unroll
                for (int j = 0; j < 4; j++) {
                    const int off = (j >> 1) * 4 + (j & 1) * 2;
                    mma16816(acc[i][j],
                             af[i * 4 + 0], af[i * 4 + 1], af[i * 4 + 2], af[i * 4 + 3],
                             bf[off], bf[off + 1]);
                }
        }
    }

    if (!DO_EXP && vtp != nullptr && n0 >= 2048) {
        // ---- V tile: apply scale+bias, store transposed into vtp (V^T [DIM, SEQ]) ----
        __syncthreads();                      // mainloop fully done; stages reusable
        __half* tile = (__half*)smc;
#pragma unroll
        for (int i = 0; i < 4; i++) {
            const int rr = mW + i * 16 + g;   // s within CTA tile
#pragma unroll
            for (int j = 0; j < 4; j++) {
                const int cc = nW + j * 8 + tg * 2;   // d within CTA tile
                float b0 = 0.f, b1 = 0.f;
                if (HAS_BIAS) { b0 = bias[n0 + cc]; b1 = bias[n0 + cc + 1]; }
                tile[cc * VT_PAD + rr]            = __float2half_rn(acc[i][j].x * scale + b0);
                tile[(cc + 1) * VT_PAD + rr]      = __float2half_rn(acc[i][j].y * scale + b1);
                tile[cc * VT_PAD + rr + 8]        = __float2half_rn(acc[i][j].z * scale + b0);
                tile[(cc + 1) * VT_PAD + rr + 8]  = __float2half_rn(acc[i][j].w * scale + b1);
            }
        }
        __syncthreads();
        const int b   = m0 >> 11;             // batch (SEQ = 2048)
        const int s0  = m0 & 2047;            // s base within batch
        const int d0  = n0 - 2048;            // d base
        __half* dst = vtp + (long long)b * DIM * SEQ;
        // 128 d-rows x 128 s-halves = 2048 chunks of 8 halves (16B)
#pragma unroll
        for (int it = 0; it < 8; it++) {
            const int idx = it * 256 + tid;
            const int d   = idx >> 4;          // 0..127
            const int sc  = (idx & 15) * 8;    // 0,8,...,120 halves
            float4 v = *(const float4*)&tile[d * VT_PAD + sc];
            *(float4*)&dst[(long long)(d0 + d) * SEQ + s0 + sc] = v;
        }
        return;
    }

    if (DO_EXP) {
        // ---- exp epilogue: write fp16 exp(scale*acc), deterministic row partials ----
        __syncthreads();                      // mainloop done; reuse stage SMEM
        float* sps = (float*)smc;             // [128 rows][4 n-groups]
        __half* C = (__half*)Cv;
#pragma unroll
        for (int i = 0; i < 4; i++) {
            const long long r = m0 + mW + i * 16 + g;
            float s0 = 0.f, s1 = 0.f;         // partials for rows r, r+8 (this thread's cols)
#pragma unroll
            for (int j = 0; j < 4; j++) {
                const int cc = n0 + nW + j * 8 + tg * 2;
                const float e0 = fast_exp(acc[i][j].x * scale);
                const float e1 = fast_exp(acc[i][j].y * scale);
                const float e2 = fast_exp(acc[i][j].z * scale);
                const float e3 = fast_exp(acc[i][j].w * scale);
                s0 += e0 + e1;
                s1 += e2 + e3;
                const long long base0 = cBase + r * ldc + cc;
                const long long base1 = base0 + 8LL * ldc;
                *(__half2*)&C[base0] = __floats2half2_rn(e0, e1);
                *(__half2*)&C[base1] = __floats2half2_rn(e2, e3);
            }
            // reduce across the 4 lanes (tg group) holding this row's 32 cols
            s0 += __shfl_xor_sync(0xffffffffu, s0, 1);
            s0 += __shfl_xor_sync(0xffffffffu, s0, 2);
            s1 += __shfl_xor_sync(0xffffffffu, s1, 1);
            s1 += __shfl_xor_sync(0xffffffffu, s1, 2);
            if (tg == 0) {
                sps[(mW + i * 16 + g) * 4 + (wid & 3)]     = s0;
                sps[(mW + i * 16 + g + 8) * 4 + (wid & 3)] = s1;
            }
        }
        __syncthreads();
        if (tid < 128) {
            // fixed-order sum over the 4 n-groups -> deterministic
            const float t = sps[tid * 4 + 0] + sps[tid * 4 + 1]
                          + sps[tid * 4 + 2] + sps[tid * 4 + 3];
            psum[((long long)blockIdx.z * SEQ + m0 + tid) * 16 + blockIdx.x] = t;
        }
        return;
    }

    // ---- Normal epilogue (per-batch stride added as ELEMENT offset) ----
#pragma unroll
    for (int i = 0; i < 4; i++) {
        const long long r = m0 + mW + i * 16 + g;
        float inv0 = 1.f, inv1 = 1.f;
        if (rowsum != nullptr) {
            inv0 = 1.0f / rowsum[blockIdx.z * SEQ + r];
            inv1 = 1.0f / rowsum[blockIdx.z * SEQ + r + 8];
        }
#pragma unroll
        for (int j = 0; j < 4; j++) {
            const int c = n0 + nW + j * 8 + tg * 2;
            float2 v0, v1;
            v0.x = acc[i][j].x * scale * inv0;
            v0.y = acc[i][j].y * scale * inv0;
            v1.x = acc[i][j].z * scale * inv1;
            v1.y = acc[i][j].w * scale * inv1;
            if (HAS_BIAS) {
                const float b0 = bias[c], b1 = bias[c + 1];
                v0.x += b0; v0.y += b1;
                v1.x += b0; v1.y += b1;
            }
            const long long base0 = cBase + r * ldc + c;
            const long long base1 = base0 + 8LL * ldc;
            if (OUT_HALF) {
                __half* C = (__half*)Cv;
                *(__half2*)&C[base0] = __floats2half2_rn(v0.x, v0.y);
                *(__half2*)&C[base1] = __floats2half2_rn(v1.x, v1.y);
            } else {
                float* C = (float*)Cv;
                *(float2*)&C[base0] = v0;
                *(float2*)&C[base1] = v1;
            }
        }
    }
}

// ---------------- rowsum reduce: 16 partials per row, fixed order ----------------
__global__ void rowsum_reduce(const float* __restrict__ psum, float* __restrict__ rowsum) {
    const int r = blockIdx.x * 256 + threadIdx.x;   // 0..8191
    const float* p = psum + (long long)r * 16;
    float s = 0.f;
#pragma unroll
    for (int i = 0; i < 16; i++) s += p[i];
    rowsum[r] = s;
}

// ---------------- fp32 -> fp16 copy ----------------
__global__ void f2h_copy(const float4* __restrict__ in, __half2* __restrict__ out, int n4) {
    const int i = blockIdx.x * blockDim.x + threadIdx.x;
    if (i < n4) {
        float4 v = in[i];
        out[i * 2]     = __floats2half2_rn(v.x, v.y);
        out[i * 2 + 1] = __floats2half2_rn(v.z, v.w);
    }
}

// ---------------- bias concat ----------------
__global__ void bias_concat(const float* __restrict__ bq, const float* __restrict__ bk,
                            const float* __restrict__ bv, float* __restrict__ out) {
    const int i = blockIdx.x * blockDim.x + threadIdx.x;
    if (i < DIM) {
        out[i] = bq[i];
        out[i + DIM] = bk[i];
        out[i + 2 * DIM] = bv[i];
    }
}

// ---------------- batched W transpose fp32 -> fp16 (z selects Wq/Wk/Wv) ----------------
__global__ void transpose_w3(const float* __restrict__ Wq, const float* __restrict__ Wk,
                             const float* __restrict__ Wv, __half* __restrict__ out) {
    __shared__ float t[32][33];
    const float* in = (blockIdx.z == 0) ? Wq : (blockIdx.z == 1) ? Wk : Wv;
    __half* o = out + (long long)blockIdx.z * DIM * DIM;
    const int bx = blockIdx.x * 32;   // col dim of in
    const int by = blockIdx.y * 32;   // row dim of in
    const int tx = threadIdx.x, ty = threadIdx.y;   // (32, 8)
#pragma unroll
    for (int i = 0; i < 32; i += 8)
        t[ty + i][tx] = in[(long long)(by + ty + i) * DIM + bx + tx];
    __syncthreads();
#pragma unroll
    for (int i = 0; i < 32; i += 8)
        o[(long long)(bx + ty + i) * DIM + by + tx] = __float2half_rn(t[tx][ty + i]);
}

extern "C" void kernel_launch(void* const* d_in, const int* in_sizes, int n_in,
                              void* d_out, int out_size) {
    (void)in_sizes; (void)n_in; (void)out_size;

    const float* x  = (const float*)d_in[0];
    const float* Wq = (const float*)d_in[1];
    const float* bq = (const float*)d_in[2];
    const float* Wk = (const float*)d_in[3];
    const float* bk = (const float*)d_in[4];
    const float* Wv = (const float*)d_in[5];
    const float* bv = (const float*)d_in[6];
    float* out = (float*)d_out;

    __half *xh, *wt, *qkv, *vt, *p;
    float *ball, *psum, *rowsum;
    cudaGetSymbolAddress((void**)&xh,   g_xh);
    cudaGetSymbolAddress((void**)&wt,   g_wt);
    cudaGetSymbolAddress((void**)&ball, g_ball);
    cudaGetSymbolAddress((void**)&qkv,  g_qkv);
    cudaGetSymbolAddress((void**)&vt,   g_vt);
    cudaGetSymbolAddress((void**)&p,    g_p);
    cudaGetSymbolAddress((void**)&psum, g_psum);
    cudaGetSymbolAddress((void**)&rowsum, g_rowsum);

    cudaFuncSetAttribute(gemm_fp16<true, true, false>,
                         cudaFuncAttributeMaxDynamicSharedMemorySize, SMEM_TOTAL);
    cudaFuncSetAttribute(gemm_fp16<false, true, true>,
                         cudaFuncAttributeMaxDynamicSharedMemorySize, SMEM_TOTAL);
    cudaFuncSetAttribute(gemm_fp16<false, false, false>,
                         cudaFuncAttributeMaxDynamicSharedMemorySize, SMEM_TOTAL);

    const int MQ = BATCH * SEQ;                     // 8192
    const long long SD3 = (long long)SEQ * 3 * DIM; // per-batch qkv stride
    const long long SS  = (long long)SEQ * SEQ;
    const long long SD  = (long long)SEQ * DIM;

    dim3 blkG(256), blkT(32, 8);

    // 0) x -> fp16
    {
        const int n4 = (int)((long long)MQ * DIM / 4);
        f2h_copy<<<(n4 + 255) / 256, 256>>>((const float4*)x, (__half2*)xh, n4);
    }
    // bias concat + batched W transposes into [3072,1024] fp16
    bias_concat<<<(DIM + 255) / 256, 256>>>(bq, bk, bv, ball);
    dim3 gWT(DIM / 32, DIM / 32, 3);
    transpose_w3<<<gWT, blkT>>>(Wq, Wk, Wv, wt);

    // 1) fused QKV: [8192,1024] @ [3072,1024]^T + bias.
    //    q,k blocks -> qkv row-major; v blocks -> vt transposed (per batch).
    dim3 gProj(3 * DIM / 128, MQ / 128, 1);       // (24, 64)
    gemm_fp16<true, true, false><<<gProj, blkG, SMEM_TOTAL>>>(
        xh, wt, ball, qkv, vt, nullptr, nullptr, DIM, DIM, DIM, 3 * DIM, 0, 0, 0, 1.0f);

    // 2) P~ = exp((Q @ K^T)/32) per batch -> fp16, + per-(row, n-tile) partials
    const __half* qh = qkv;
    const __half* kh = qkv + DIM;
    dim3 gScore(SEQ / 128, SEQ / 128, BATCH);     // (16, 16, 4)
    gemm_fp16<false, true, true><<<gScore, blkG, SMEM_TOTAL>>>(
        qh, kh, nullptr, p, nullptr, psum, nullptr,
        DIM, 3 * DIM, 3 * DIM, SEQ, SD3, SD3, SS, 0.03125f);

    // 3) rowsum[8192] = sum of 16 partials per row (fixed order, deterministic)
    rowsum_reduce<<<MQ / 256, 256>>>(psum, rowsum);

    // 4) out = (P~ @ V) / rowsum per batch -> fp32
    dim3 gOut(DIM / 128, SEQ / 128, BATCH);       // (8, 16, 4)
    gemm_fp16<false, false, false><<<gOut, blkG, SMEM_TOTAL>>>(
        p, vt, nullptr, out, nullptr, nullptr, rowsum,
        SEQ, SEQ, SEQ, DIM, SS, SD, SD, 1.0f);
}